// round 9
// baseline (speedup 1.0000x reference)
#include <cuda_runtime.h>
#include <math.h>
#include <stdint.h>

// Problem constants
#define S_LEN   2048
#define D_MODEL 1024
#define NHEAD   16
#define HDIM    64
#define BATCH   4
#define BH      (BATCH * NHEAD)   // 64

// Scratch (device globals — no allocation allowed)
__device__ float g_q[(size_t)BH * S_LEN * HDIM];          // [B,H,S,hd] rope'd, pre-scaled, tf32
__device__ float g_k[(size_t)BH * S_LEN * HDIM];          // [B,H,S,hd]
__device__ float g_v[(size_t)BH * S_LEN * HDIM];          // [B,H,S,hd]
__device__ float g_attn[(size_t)BATCH * S_LEN * D_MODEL]; // [B,S,D], tf32-rounded
__device__ float g_cos[S_LEN * (HDIM / 2)];
__device__ float g_sin[S_LEN * (HDIM / 2)];
__device__ float g_xc[(size_t)BATCH * S_LEN * D_MODEL];   // tf32-rounded x
__device__ float g_wc[(size_t)3 * D_MODEL * D_MODEL];     // tf32-rounded w_qkv
__device__ float g_woc[(size_t)D_MODEL * D_MODEL];        // tf32-rounded w_o
__device__ float g_bias[BATCH * S_LEN];                   // 0 or -1e30 padding bias

// ---------------------------------------------------------------------------
// helpers
// ---------------------------------------------------------------------------
__device__ __forceinline__ float to_tf32(float x) {
    float r;
    asm("cvt.rna.tf32.f32 %0, %1;" : "=f"(r) : "f"(x));
    return r;
}

__device__ __forceinline__ void mma_m16n8k8(
    float* c, float a0, float a1, float a2, float a3, float b0, float b1)
{
    uint32_t ua0 = __float_as_uint(a0), ua1 = __float_as_uint(a1);
    uint32_t ua2 = __float_as_uint(a2), ua3 = __float_as_uint(a3);
    uint32_t ub0 = __float_as_uint(b0), ub1 = __float_as_uint(b1);
    asm volatile(
        "mma.sync.aligned.m16n8k8.row.col.f32.tf32.tf32.f32 "
        "{%0,%1,%2,%3}, {%4,%5,%6,%7}, {%8,%9}, {%0,%1,%2,%3};"
        : "+f"(c[0]), "+f"(c[1]), "+f"(c[2]), "+f"(c[3])
        : "r"(ua0), "r"(ua1), "r"(ua2), "r"(ua3), "r"(ub0), "r"(ub1));
}

__device__ __forceinline__ uint32_t smem_u32(const void* p) {
    return (uint32_t)__cvta_generic_to_shared(p);
}
#define CP16(d, s)  asm volatile("cp.async.ca.shared.global [%0], [%1], 16;" :: "r"(d), "l"(s))
#define CP_COMMIT   asm volatile("cp.async.commit_group;")
#define CP_WAIT0    asm volatile("cp.async.wait_group 0;")
#define CP_WAIT1    asm volatile("cp.async.wait_group 1;")

// ---------------------------------------------------------------------------
// prep kernels
// ---------------------------------------------------------------------------
__global__ void rope_table_kernel() {
    int idx = blockIdx.x * blockDim.x + threadIdx.x;
    if (idx >= S_LEN * (HDIM / 2)) return;
    int s = idx >> 5;
    int i = idx & 31;
    float inv = exp2f(-13.287712379549449f * (2.0f * (float)i / 64.0f));
    float ang = (float)s * inv;
    float sn, cs;
    sincosf(ang, &sn, &cs);
    g_cos[idx] = cs;
    g_sin[idx] = sn;
}

#define N4_X  2097152
#define N4_W  786432
#define N4_WO 262144
__global__ void cvt_all_kernel(const float4* __restrict__ x,
                               const float4* __restrict__ w,
                               const float4* __restrict__ wo) {
    int i = blockIdx.x * blockDim.x + threadIdx.x;
    const float4* src;
    float4* dst;
    if (i < N4_X)                    { src = x + i;                 dst = (float4*)g_xc + i; }
    else if (i < N4_X + N4_W)        { src = w + (i - N4_X);        dst = (float4*)g_wc + (i - N4_X); }
    else if (i < N4_X + N4_W + N4_WO){ src = wo + (i - N4_X - N4_W);dst = (float4*)g_woc + (i - N4_X - N4_W); }
    else return;
    float4 v = *src;
    *dst = make_float4(to_tf32(v.x), to_tf32(v.y), to_tf32(v.z), to_tf32(v.w));
}

__global__ void bias_kernel(const int* __restrict__ pmask) {
    int i = blockIdx.x * blockDim.x + threadIdx.x;
    if (i < BATCH * S_LEN)
        g_bias[i] = (pmask[i] == 0) ? -1e30f : 0.0f;
}

// ---------------------------------------------------------------------------
// tf32 tensor-core GEMM: C[m,n] = sum_k A[m,k] * Bw[n,k]   (K = 1024)
// CTA tile 128(m) x 256(n), 8 warps at 64x64 warp tiles (balanced LDS:MMA).
// BK=32, 3-stage cp.async ring, ONE barrier per tile, XOR-swizzled smem
// (row stride 32 floats, 16B-chunk ^= row&7), LDS.128 fragment loads
// feeding 2 MMAs each.
// MODE 0: qkv projection -> RoPE + 0.125 q-scale + head-scatter (tf32)
// MODE 1: plain fp32 store to Out
// ---------------------------------------------------------------------------
#define MMA_ST_FL 4096                 // A stage floats (128 x 32)
#define MMB_ST_FL 8192                 // B stage floats (256 x 32)
#define MM_SM_BYTES ((3 * MMA_ST_FL + 3 * MMB_ST_FL) * 4)   // 147456

__device__ __forceinline__ void mm_stage(
    uint32_t sA, uint32_t sB, const float* Ag, const float* Bg, int tid)
{
#pragma unroll
    for (int i = 0; i < 4; ++i) {              // A: 128 rows x 8 chunks
        int idx = tid + i * 256;
        int r   = idx >> 3;
        int ch  = idx & 7;
        CP16(sA + r * 128 + ((ch ^ (r & 7)) << 4), Ag + (size_t)r * 1024 + ch * 4);
    }
#pragma unroll
    for (int i = 0; i < 8; ++i) {              // B: 256 rows x 8 chunks
        int idx = tid + i * 256;
        int r   = idx >> 3;
        int ch  = idx & 7;
        CP16(sB + r * 128 + ((ch ^ (r & 7)) << 4), Bg + (size_t)r * 1024 + ch * 4);
    }
}

template<int MODE>
__global__ __launch_bounds__(256, 1) void mm_tf32(
    const float* __restrict__ A, const float* __restrict__ Bw,
    float* __restrict__ Out)
{
    extern __shared__ float smbuf[];
    // A stages: smbuf + s*4096 ; B stages: smbuf + 12288 + s*8192

    const int tid    = threadIdx.x;
    const int m_base = blockIdx.y * 128;
    const int n_base = blockIdx.x * 256;

    const float* Ag = A  + (size_t)m_base * 1024;
    const float* Bg = Bw + (size_t)n_base * 1024;

    const int warp = tid >> 5;
    const int lane = tid & 31;
    const int wm = warp & 1;           // 0..1 -> rows wm*64
    const int wn = warp >> 1;          // 0..3 -> cols wn*64
    const int g  = lane >> 2;
    const int tg = lane & 3;

    float acc[4][8][4];
#pragma unroll
    for (int mi = 0; mi < 4; mi++)
#pragma unroll
        for (int ni = 0; ni < 8; ni++)
#pragma unroll
            for (int j = 0; j < 4; j++) acc[mi][ni][j] = 0.0f;

    const uint32_t sab = smem_u32(smbuf);
    // prologue: stage tiles 0, 1
#pragma unroll
    for (int p = 0; p < 2; ++p) {
        mm_stage(sab + p * MMA_ST_FL * 4,
                 sab + (3 * MMA_ST_FL + p * MMB_ST_FL) * 4,
                 Ag + p * 32, Bg + p * 32, tid);
        CP_COMMIT;
    }

    int sidx = 0;
    for (int kt = 0; kt < 32; ++kt) {
        CP_WAIT1;          // tile kt staged
        __syncthreads();   // visibility + readers of tile kt-1 done

        {   // prefetch tile kt+2 into stage (sidx+2)%3 (= stage of tile kt-1)
            int ps = sidx + 2; if (ps >= 3) ps -= 3;
            if (kt + 2 < 32)
                mm_stage(sab + ps * MMA_ST_FL * 4,
                         sab + (3 * MMA_ST_FL + ps * MMB_ST_FL) * 4,
                         Ag + (kt + 2) * 32, Bg + (kt + 2) * 32, tid);
            CP_COMMIT;
        }

        const float* Asb = smbuf + sidx * MMA_ST_FL;
        const float* Bsb = smbuf + 3 * MMA_ST_FL + sidx * MMB_ST_FL;
#pragma unroll
        for (int j = 0; j < 2; ++j) {           // k16 step: 16 LDS.128, 64 MMAs
            const int sw = (((tg + 4 * j) ^ g) << 2);
            float4 af[4][2];
#pragma unroll
            for (int mi = 0; mi < 4; mi++) {
                int r = wm * 64 + mi * 16 + g;
                af[mi][0] = *(const float4*)&Asb[r * 32 + sw];
                af[mi][1] = *(const float4*)&Asb[(r + 8) * 32 + sw];
            }
#pragma unroll
            for (int ni = 0; ni < 8; ++ni) {
                float4 bf = *(const float4*)&Bsb[(wn * 64 + ni * 8 + g) * 32 + sw];
#pragma unroll
                for (int mi = 0; mi < 4; mi++) {
                    mma_m16n8k8(acc[mi][ni],
                                af[mi][0].x, af[mi][1].x,
                                af[mi][0].y, af[mi][1].y,
                                bf.x, bf.y);
                    mma_m16n8k8(acc[mi][ni],
                                af[mi][0].z, af[mi][1].z,
                                af[mi][0].w, af[mi][1].w,
                                bf.z, bf.w);
                }
            }
        }
        if (++sidx == 3) sidx = 0;
    }

    // epilogue: warp tile spans 64 cols from a 64-aligned base -> single head/part
    {
        const int n0   = n_base + wn * 64;
        const int part = n0 >> 10;
        const int h    = (n0 & 1023) >> 6;
#pragma unroll
        for (int mi = 0; mi < 4; mi++) {
            int row0 = m_base + wm * 64 + mi * 16 + g;
#pragma unroll
            for (int ni = 0; ni < 8; ni++) {
                int d0 = ni * 8 + 2 * tg;
                if (MODE == 0) {
                    int i0 = d0 >> 1;
                    float* dst = (part == 0) ? g_q : (part == 1) ? g_k : g_v;
#pragma unroll
                    for (int half = 0; half < 2; half++) {
                        int m = row0 + half * 8;
                        int b = m >> 11, s = m & 2047;
                        float v0 = acc[mi][ni][half * 2 + 0];
                        float v1 = acc[mi][ni][half * 2 + 1];
                        if (part < 2) {
                            float cs = g_cos[s * 32 + i0], sn = g_sin[s * 32 + i0];
                            float r0 = v0 * cs - v1 * sn;
                            float r1 = v0 * sn + v1 * cs;
                            if (part == 0) { r0 *= 0.125f; r1 *= 0.125f; }
                            v0 = r0; v1 = r1;
                        }
                        *(float2*)(dst + (((size_t)(b * NHEAD + h) * S_LEN + s) * HDIM + d0))
                            = make_float2(to_tf32(v0), to_tf32(v1));
                    }
                } else {
                    int coln = n0 + d0;
#pragma unroll
                    for (int half = 0; half < 2; half++) {
                        int m = row0 + half * 8;
                        *(float2*)(Out + (size_t)m * 1024 + coln)
                            = make_float2(acc[mi][ni][half * 2 + 0],
                                          acc[mi][ni][half * 2 + 1]);
                    }
                }
            }
        }
    }
}

// ---------------------------------------------------------------------------
// Tensor-core flash attention (tf32 mma.sync): swizzled Q/K (LDS.128 QK^T
// fragments) + row-major V (conflict-lite float-pair PV loads).
// q-tile 128 rows, k-tile 64 keys, 2-stage cp.async, ONE barrier per k-tile.
// Q pre-scaled by 1/8 at the QKV epilogue.
// ---------------------------------------------------------------------------
// Smem floats: Qs 128*64 (swizzled), Ks 2*64*64 (swizzled), Vs 2*64*68, PM 2*64
#define ATTN_SM_FLOATS (8192 + 8192 + 8704 + 128)
#define ATTN_SM_BYTES  (ATTN_SM_FLOATS * 4)

__device__ __forceinline__ void stage_kv(
    float* Kdst, float* Vdst, float* PMdst,
    const float* Kg_tile, const float* Vg_tile, const float* Bsrc, int tid)
{
#pragma unroll
    for (int i = 0; i < 4; ++i) {
        int idx = tid + i * 256;
        int row = idx >> 4;          // key row 0..63
        int ch  = idx & 15;          // 16B chunk
        CP16(smem_u32(Kdst + row * 64 + ((ch ^ (row & 7)) << 2)),
             Kg_tile + (size_t)row * 64 + ch * 4);
        CP16(smem_u32(Vdst + row * 68 + ch * 4),
             Vg_tile + (size_t)row * 64 + ch * 4);
    }
    if (tid < 16) CP16(smem_u32(PMdst + tid * 4), Bsrc + tid * 4);
}

__global__ __launch_bounds__(256, 2) void attn_tc()
{
    extern __shared__ float sm[];
    float* Qs = sm;                 // [128][64] swizzled
    float* Ks = Qs + 8192;          // [2][64][64] swizzled
    float* Vs = Ks + 8192;          // [2][64][68]
    float* PM = Vs + 8704;          // [2][64]

    const int qt    = 15 - (int)blockIdx.x;         // heavy tiles first
    const int qbase = qt * 128;
    const int bh = blockIdx.y;
    const int b  = bh >> 4, h = bh & 15;
    const int tid  = threadIdx.x;
    const int warp = tid >> 5, lane = tid & 31;
    const int g = lane >> 2, tg = lane & 3;
    const int nkt = 2 * (qt + 1);

    const float* Kg = g_k + (size_t)bh * S_LEN * HDIM;
    const float* Vg = g_v + (size_t)bh * S_LEN * HDIM;
    const float* Bg = g_bias + b * S_LEN;

    stage_kv(Ks, Vs, PM, Kg, Vg, Bg, tid);
    CP_COMMIT;

    {
        const float* Qg = g_q + ((size_t)bh * S_LEN + qbase) * HDIM;
#pragma unroll
        for (int r = 0; r < 8; ++r) {
            int idx = tid + r * 256;
            int row = idx >> 4, ch = idx & 15;
            *(float4*)&Qs[row * 64 + ((ch ^ (row & 7)) << 2)]
                = *(const float4*)&Qg[row * 64 + ch * 4];
        }
    }

    float S[8][4], O[8][4], mrow[2], lrow[2];
    mrow[0] = mrow[1] = -INFINITY;
    lrow[0] = lrow[1] = 0.0f;
#pragma unroll
    for (int t = 0; t < 8; t++)
#pragma unroll
        for (int j = 0; j < 4; j++) O[t][j] = 0.0f;

    const int wrow0 = qbase + warp * 16;

    for (int kt = 0; kt < nkt; ++kt) {
        const int buf   = kt & 1;
        const int kbase = kt * 64;

        CP_WAIT0;
        __syncthreads();

        if (kt + 1 < nkt) {
            int nb  = buf ^ 1;
            int kb2 = (kt + 1) * 64;
            stage_kv(Ks + nb * 4096, Vs + nb * 4352, PM + nb * 64,
                     Kg + (size_t)kb2 * 64, Vg + (size_t)kb2 * 64, Bg + kb2, tid);
        }
        CP_COMMIT;

        if (kbase <= wrow0 + 15) {     // per-warp causal tile skip
            const float* Kb  = Ks + buf * 4096;
            const float* Vb  = Vs + buf * 4352;
            const float* PMb = PM + buf * 64;

#pragma unroll
            for (int nt = 0; nt < 8; nt++)
#pragma unroll
                for (int j = 0; j < 4; j++) S[nt][j] = 0.0f;

            const int qrow = (warp * 16 + g) * 64;
#pragma unroll
            for (int j = 0; j < 4; ++j) {
                const int sw = (((tg + 4 * j) ^ g) << 2);
                float4 a0 = *(const float4*)&Qs[qrow + sw];
                float4 a1 = *(const float4*)&Qs[qrow + 8 * 64 + sw];
#pragma unroll
                for (int nt = 0; nt < 8; ++nt) {
                    float4 kb = *(const float4*)&Kb[(nt * 8 + g) * 64 + sw];
                    mma_m16n8k8(S[nt], a0.x, a1.x, a0.y, a1.y, kb.x, kb.y);
                    mma_m16n8k8(S[nt], a0.z, a1.z, a0.w, a1.w, kb.z, kb.w);
                }
            }

            float2 pmb[8];
#pragma unroll
            for (int nt = 0; nt < 8; nt++)
                pmb[nt] = *(const float2*)&PMb[nt * 8 + 2 * tg];

            const bool do_causal = (kbase + 63 > wrow0);

            {
                int row_lo = wrow0 + g;
                int row_hi = row_lo + 8;
                float mx_lo = -INFINITY, mx_hi = -INFINITY;
#pragma unroll
                for (int nt = 0; nt < 8; nt++) {
                    int col0 = kbase + nt * 8 + 2 * tg;
                    float v0 = S[nt][0] + pmb[nt].x;
                    float v1 = S[nt][1] + pmb[nt].y;
                    float v2 = S[nt][2] + pmb[nt].x;
                    float v3 = S[nt][3] + pmb[nt].y;
                    if (do_causal) {
                        if (col0     > row_lo) v0 = -1e30f;
                        if (col0 + 1 > row_lo) v1 = -1e30f;
                        if (col0     > row_hi) v2 = -1e30f;
                        if (col0 + 1 > row_hi) v3 = -1e30f;
                    }
                    S[nt][0] = v0; S[nt][1] = v1;
                    S[nt][2] = v2; S[nt][3] = v3;
                    mx_lo = fmaxf(mx_lo, fmaxf(v0, v1));
                    mx_hi = fmaxf(mx_hi, fmaxf(v2, v3));
                }
                mx_lo = fmaxf(mx_lo, __shfl_xor_sync(0xffffffffu, mx_lo, 1));
                mx_lo = fmaxf(mx_lo, __shfl_xor_sync(0xffffffffu, mx_lo, 2));
                mx_hi = fmaxf(mx_hi, __shfl_xor_sync(0xffffffffu, mx_hi, 1));
                mx_hi = fmaxf(mx_hi, __shfl_xor_sync(0xffffffffu, mx_hi, 2));

                float mn_lo = fmaxf(mrow[0], mx_lo);
                float mn_hi = fmaxf(mrow[1], mx_hi);
                float al_lo = __expf(mrow[0] - mn_lo);
                float al_hi = __expf(mrow[1] - mn_hi);

                float s_lo = 0.0f, s_hi = 0.0f;
#pragma unroll
                for (int nt = 0; nt < 8; nt++) {
                    float p0 = __expf(S[nt][0] - mn_lo);
                    float p1 = __expf(S[nt][1] - mn_lo);
                    float p2 = __expf(S[nt][2] - mn_hi);
                    float p3 = __expf(S[nt][3] - mn_hi);
                    s_lo += p0 + p1;
                    s_hi += p2 + p3;
                    S[nt][0] = to_tf32(p0);
                    S[nt][1] = to_tf32(p1);
                    S[nt][2] = to_tf32(p2);
                    S[nt][3] = to_tf32(p3);
                }
                s_lo += __shfl_xor_sync(0xffffffffu, s_lo, 1);
                s_lo += __shfl_xor_sync(0xffffffffu, s_lo, 2);
                s_hi += __shfl_xor_sync(0xffffffffu, s_hi, 1);
                s_hi += __shfl_xor_sync(0xffffffffu, s_hi, 2);

                lrow[0] = lrow[0] * al_lo + s_lo;
                lrow[1] = lrow[1] * al_hi + s_hi;
                mrow[0] = mn_lo;
                mrow[1] = mn_hi;
#pragma unroll
                for (int hd = 0; hd < 8; hd++) {
                    O[hd][0] *= al_lo;
                    O[hd][1] *= al_lo;
                    O[hd][2] *= al_hi;
                    O[hd][3] *= al_hi;
                }
            }

#pragma unroll
            for (int ks = 0; ks < 8; ++ks) {
#pragma unroll
                for (int hd = 0; hd < 8; ++hd) {
                    float b0 = Vb[(ks * 8 + 2 * tg    ) * 68 + hd * 8 + g];
                    float b1 = Vb[(ks * 8 + 2 * tg + 1) * 68 + hd * 8 + g];
                    mma_m16n8k8(O[hd], S[ks][0], S[ks][2],
                                       S[ks][1], S[ks][3], b0, b1);
                }
            }
        }
    }

    {
        float inv_lo = 1.0f / lrow[0];
        float inv_hi = 1.0f / lrow[1];
        int row_lo = wrow0 + g;
#pragma unroll
        for (int hd = 0; hd < 8; hd++) {
            int col = h * 64 + hd * 8 + 2 * tg;
            *(float2*)(g_attn + ((size_t)b * S_LEN + row_lo) * D_MODEL + col) =
                make_float2(to_tf32(O[hd][0] * inv_lo),
                            to_tf32(O[hd][1] * inv_lo));
            *(float2*)(g_attn + ((size_t)b * S_LEN + row_lo + 8) * D_MODEL + col) =
                make_float2(to_tf32(O[hd][2] * inv_hi),
                            to_tf32(O[hd][3] * inv_hi));
        }
    }
}

// ---------------------------------------------------------------------------
extern "C" void kernel_launch(void* const* d_in, const int* in_sizes, int n_in,
                              void* d_out, int out_size)
{
    const float* x      = (const float*)d_in[0];
    const int*   pmask  = (const int*)d_in[1];
    const float* w_qkv  = (const float*)d_in[2];
    const float* w_o    = (const float*)d_in[3];
    float*       out    = (float*)d_out;

    cudaFuncSetAttribute(attn_tc,
                         cudaFuncAttributeMaxDynamicSharedMemorySize, ATTN_SM_BYTES);
    cudaFuncSetAttribute(mm_tf32<0>,
                         cudaFuncAttributeMaxDynamicSharedMemorySize, MM_SM_BYTES);
    cudaFuncSetAttribute(mm_tf32<1>,
                         cudaFuncAttributeMaxDynamicSharedMemorySize, MM_SM_BYTES);

    float *xc, *wc, *woc, *attn_ptr;
    cudaGetSymbolAddress((void**)&xc, g_xc);
    cudaGetSymbolAddress((void**)&wc, g_wc);
    cudaGetSymbolAddress((void**)&woc, g_woc);
    cudaGetSymbolAddress((void**)&attn_ptr, g_attn);

    rope_table_kernel<<<(S_LEN * 32 + 255) / 256, 256>>>();
    cvt_all_kernel<<<(N4_X + N4_W + N4_WO + 255) / 256, 256>>>(
        (const float4*)x, (const float4*)w_qkv, (const float4*)w_o);
    bias_kernel<<<(BATCH * S_LEN + 255) / 256, 256>>>(pmask);

    // QKV projection + RoPE: M=8192, N=3072 (CTA 128x256)
    mm_tf32<0><<<dim3(3 * D_MODEL / 256, (BATCH * S_LEN) / 128), 256, MM_SM_BYTES>>>(xc, wc, nullptr);
    // Flash attention (mma.sync tensor cores)
    attn_tc<<<dim3(16, BH), 256, ATTN_SM_BYTES>>>();
    // Output projection: M=8192, N=1024 (CTA 128x256)
    mm_tf32<1><<<dim3(D_MODEL / 256, (BATCH * S_LEN) / 128), 256, MM_SM_BYTES>>>(attn_ptr, woc, out);
}

// round 13
// speedup vs baseline: 1.4412x; 1.4412x over previous
#include <cuda_runtime.h>
#include <cuda_fp16.h>
#include <math.h>
#include <stdint.h>

// Problem constants
#define S_LEN   2048
#define D_MODEL 1024
#define NHEAD   16
#define HDIM    64
#define BATCH   4
#define BH      (BATCH * NHEAD)   // 64

// Scratch (device globals — no allocation allowed)
__device__ float  g_q[(size_t)BH * S_LEN * HDIM];          // [B,H,S,hd] rope'd, pre-scaled, tf32
__device__ float  g_k[(size_t)BH * S_LEN * HDIM];
__device__ float  g_v[(size_t)BH * S_LEN * HDIM];
__device__ __half g_attn[(size_t)BATCH * S_LEN * D_MODEL]; // [B,S,D] fp16, k-permuted
__device__ float  g_cos[S_LEN * (HDIM / 2)];
__device__ float  g_sin[S_LEN * (HDIM / 2)];
__device__ __half g_xc[(size_t)BATCH * S_LEN * D_MODEL];   // fp16, k-permuted
__device__ __half g_wc[(size_t)3 * D_MODEL * D_MODEL];     // fp16, k-permuted
__device__ __half g_woc[(size_t)D_MODEL * D_MODEL];        // fp16, k-permuted
__device__ float  g_bias[BATCH * S_LEN];                   // 0 or -1e30 padding bias

// ---------------------------------------------------------------------------
// helpers
// ---------------------------------------------------------------------------
__device__ __forceinline__ float to_tf32(float x) {
    float r;
    asm("cvt.rna.tf32.f32 %0, %1;" : "=f"(r) : "f"(x));
    return r;
}

// tf32 m16n8k8 (used by attention)
__device__ __forceinline__ void mma_m16n8k8(
    float* c, float a0, float a1, float a2, float a3, float b0, float b1)
{
    uint32_t ua0 = __float_as_uint(a0), ua1 = __float_as_uint(a1);
    uint32_t ua2 = __float_as_uint(a2), ua3 = __float_as_uint(a3);
    uint32_t ub0 = __float_as_uint(b0), ub1 = __float_as_uint(b1);
    asm volatile(
        "mma.sync.aligned.m16n8k8.row.col.f32.tf32.tf32.f32 "
        "{%0,%1,%2,%3}, {%4,%5,%6,%7}, {%8,%9}, {%0,%1,%2,%3};"
        : "+f"(c[0]), "+f"(c[1]), "+f"(c[2]), "+f"(c[3])
        : "r"(ua0), "r"(ua1), "r"(ua2), "r"(ua3), "r"(ub0), "r"(ub1));
}

// fp16 m16n8k16 (GEMMs)
__device__ __forceinline__ void mma_fp16(
    float* c, uint32_t a0, uint32_t a1, uint32_t a2, uint32_t a3,
    uint32_t b0, uint32_t b1)
{
    asm volatile(
        "mma.sync.aligned.m16n8k16.row.col.f32.f16.f16.f32 "
        "{%0,%1,%2,%3}, {%4,%5,%6,%7}, {%8,%9}, {%0,%1,%2,%3};"
        : "+f"(c[0]), "+f"(c[1]), "+f"(c[2]), "+f"(c[3])
        : "r"(a0), "r"(a1), "r"(a2), "r"(a3), "r"(b0), "r"(b1));
}

__device__ __forceinline__ uint32_t smem_u32(const void* p) {
    return (uint32_t)__cvta_generic_to_shared(p);
}
#define CP16(d, s)  asm volatile("cp.async.ca.shared.global [%0], [%1], 16;" :: "r"(d), "l"(s))
#define CP_COMMIT   asm volatile("cp.async.commit_group;")
#define CP_WAIT0    asm volatile("cp.async.wait_group 0;")
#define CP_WAIT1    asm volatile("cp.async.wait_group 1;")

// k-permutation within 32-blocks: phys(l) = 8*((l>>1)&3) + 2*(l>>3) + (l&1).
// One LDS.128 per thread then yields both k16 fragment pairs for a k32 step.
__device__ __forceinline__ uint32_t kperm32(uint32_t l) {
    return 8u * ((l >> 1) & 3u) + 2u * (l >> 3) + (l & 1u);
}

// ---------------------------------------------------------------------------
// prep kernels
// ---------------------------------------------------------------------------
__global__ void rope_table_kernel() {
    int idx = blockIdx.x * blockDim.x + threadIdx.x;
    if (idx >= S_LEN * (HDIM / 2)) return;
    int s = idx >> 5;
    int i = idx & 31;
    float inv = exp2f(-13.287712379549449f * (2.0f * (float)i / 64.0f));
    float ang = (float)s * inv;
    float sn, cs;
    sincosf(ang, &sn, &cs);
    g_cos[idx] = cs;
    g_sin[idx] = sn;
}

// fp32 -> fp16 with k-permutation (pairs stay adjacent under the permutation).
#define N2_X  4194304u
#define N2_W  1572864u
#define N2_WO 524288u
__global__ void cvt_all_kernel(const float2* __restrict__ x,
                               const float2* __restrict__ w,
                               const float2* __restrict__ wo) {
    uint32_t i = blockIdx.x * blockDim.x + threadIdx.x;
    const float2* src;
    __half* dst;
    size_t e;
    if (i < N2_X)                  { src = x  + i;                  dst = g_xc;  e = (size_t)i * 2; }
    else if (i < N2_X + N2_W)      { src = w  + (i - N2_X);         dst = g_wc;  e = (size_t)(i - N2_X) * 2; }
    else if (i < N2_X + N2_W + N2_WO) { src = wo + (i - N2_X - N2_W); dst = g_woc; e = (size_t)(i - N2_X - N2_W) * 2; }
    else return;
    float2 v = *src;
    size_t pos = (e & ~(size_t)31) + kperm32((uint32_t)(e & 31));
    *(__half2*)(dst + pos) = __float22half2_rn(v);
}

__global__ void bias_kernel(const int* __restrict__ pmask) {
    int i = blockIdx.x * blockDim.x + threadIdx.x;
    if (i < BATCH * S_LEN)
        g_bias[i] = (pmask[i] == 0) ? -1e30f : 0.0f;
}

// ---------------------------------------------------------------------------
// fp16 tensor-core GEMM: C[m,n] = sum_k A[m,k] * Bw[n,k]   (K = 1024, fp16 in,
// fp32 acc). CTA 128x128, 256 threads = 8 warps, warp grid 2(m) x 4(n),
// warp tile 64x32. BK=32, 3-stage cp.async ring, ONE barrier/tile.
// Smem rows 64B, 16B-chunk XOR swizzle (ch ^= row&3). Operands k-permuted in
// gmem so each LDS.128 gives a full m16n8k16 fragment pair for k32.
// MODE 0: qkv -> RoPE + 0.125 q-scale + head-scatter (fp32 tf32-rounded)
// MODE 1: plain fp32 store to Out
// ---------------------------------------------------------------------------
#define MMH_STAGE_BYTES 8192                    // 128 rows x 64B
#define MMH_SM_BYTES    (6 * MMH_STAGE_BYTES)   // 3 stages x (A+B) = 48KB

__device__ __forceinline__ void mmh_stage(
    uint32_t sA, uint32_t sB, const __half* Ag, const __half* Bg, int tid)
{
#pragma unroll
    for (int i = 0; i < 2; ++i) {
        int idx = tid + i * 256;      // 0..511
        int r   = idx >> 2;           // row 0..127
        int ch  = idx & 3;            // 16B chunk 0..3
        uint32_t so = (uint32_t)(r * 64 + ((ch ^ (r & 3)) << 4));
        CP16(sA + so, Ag + (size_t)r * 1024 + ch * 8);
        CP16(sB + so, Bg + (size_t)r * 1024 + ch * 8);
    }
}

template<int MODE>
__global__ __launch_bounds__(256, 2) void mm_fp16(
    const __half* __restrict__ A, const __half* __restrict__ Bw,
    float* __restrict__ Out)
{
    extern __shared__ __half smh[];
    // A stages: bytes [s*8192), B stages: bytes 24576 + s*8192

    const int tid    = threadIdx.x;
    const int m_base = blockIdx.y * 128;
    const int n_base = blockIdx.x * 128;

    const __half* Ag = A  + (size_t)m_base * 1024;
    const __half* Bg = Bw + (size_t)n_base * 1024;

    const int warp = tid >> 5;
    const int lane = tid & 31;
    const int wm = warp & 1;           // rows wm*64
    const int wn = warp >> 1;          // cols wn*32  (0..3)
    const int g  = lane >> 2;
    const int tg = lane & 3;

    float acc[4][4][4];
#pragma unroll
    for (int mi = 0; mi < 4; mi++)
#pragma unroll
        for (int ni = 0; ni < 4; ni++)
#pragma unroll
            for (int j = 0; j < 4; j++) acc[mi][ni][j] = 0.0f;

    const uint32_t sb = smem_u32(smh);
    // prologue: stage tiles 0, 1
#pragma unroll
    for (int p = 0; p < 2; ++p) {
        mmh_stage(sb + p * MMH_STAGE_BYTES,
                  sb + 3 * MMH_STAGE_BYTES + p * MMH_STAGE_BYTES,
                  Ag + p * 32, Bg + p * 32, tid);
        CP_COMMIT;
    }

    int sidx = 0;
    for (int kt = 0; kt < 32; ++kt) {
        CP_WAIT1;          // tile kt staged
        __syncthreads();   // visibility + readers of tile kt-1 done

        {   // prefetch tile kt+2 into stage (sidx+2)%3 (= stage of tile kt-1)
            int ps = sidx + 2; if (ps >= 3) ps -= 3;
            if (kt + 2 < 32)
                mmh_stage(sb + ps * MMH_STAGE_BYTES,
                          sb + 3 * MMH_STAGE_BYTES + ps * MMH_STAGE_BYTES,
                          Ag + (kt + 2) * 32, Bg + (kt + 2) * 32, tid);
            CP_COMMIT;
        }

        const __half* Asb = smh + sidx * 4096;           // halves
        const __half* Bsb = smh + 12288 + sidx * 4096;

        uint4 af[4][2], bf[4];
#pragma unroll
        for (int mi = 0; mi < 4; mi++) {
            int r0 = wm * 64 + mi * 16 + g;
            af[mi][0] = *(const uint4*)&Asb[r0 * 32 + ((tg ^ (r0 & 3)) << 3)];
            int r1 = r0 + 8;   // (r1 & 3) == (r0 & 3)
            af[mi][1] = *(const uint4*)&Asb[r1 * 32 + ((tg ^ (r1 & 3)) << 3)];
        }
#pragma unroll
        for (int ni = 0; ni < 4; ni++) {
            int rb = wn * 32 + ni * 8 + g;
            bf[ni] = *(const uint4*)&Bsb[rb * 32 + ((tg ^ (rb & 3)) << 3)];
        }
        // k16 step 0: .x/.y ; step 1: .z/.w  (phys layout guarantees this)
#pragma unroll
        for (int mi = 0; mi < 4; mi++)
#pragma unroll
            for (int ni = 0; ni < 4; ni++) {
                mma_fp16(acc[mi][ni],
                         af[mi][0].x, af[mi][1].x, af[mi][0].y, af[mi][1].y,
                         bf[ni].x, bf[ni].y);
                mma_fp16(acc[mi][ni],
                         af[mi][0].z, af[mi][1].z, af[mi][0].w, af[mi][1].w,
                         bf[ni].z, bf[ni].w);
            }
        if (++sidx == 3) sidx = 0;
    }

    // epilogue: warp n-tile = 32 cols, fully inside one head (32-aligned base)
    {
        const int n0   = n_base + wn * 32;
        const int part = n0 >> 10;          // 0=q,1=k,2=v (MODE 0)
        const int h    = (n0 & 1023) >> 6;
        const int dbase = n0 & 63;          // 0 or 32
#pragma unroll
        for (int mi = 0; mi < 4; mi++) {
            int row0 = m_base + wm * 64 + mi * 16 + g;
#pragma unroll
            for (int ni = 0; ni < 4; ni++) {
                if (MODE == 0) {
                    int d0 = dbase + ni * 8 + 2 * tg;
                    int i0 = d0 >> 1;
                    float* dst = (part == 0) ? g_q : (part == 1) ? g_k : g_v;
#pragma unroll
                    for (int half = 0; half < 2; half++) {
                        int m = row0 + half * 8;
                        int b = m >> 11, s = m & 2047;
                        float v0 = acc[mi][ni][half * 2 + 0];
                        float v1 = acc[mi][ni][half * 2 + 1];
                        if (part < 2) {
                            float cs = g_cos[s * 32 + i0], sn = g_sin[s * 32 + i0];
                            float r0 = v0 * cs - v1 * sn;
                            float r1 = v0 * sn + v1 * cs;
                            if (part == 0) { r0 *= 0.125f; r1 *= 0.125f; }
                            v0 = r0; v1 = r1;
                        }
                        *(float2*)(dst + (((size_t)(b * NHEAD + h) * S_LEN + s) * HDIM + d0))
                            = make_float2(to_tf32(v0), to_tf32(v1));
                    }
                } else {
                    int coln = n0 + ni * 8 + 2 * tg;
#pragma unroll
                    for (int half = 0; half < 2; half++) {
                        int m = row0 + half * 8;
                        *(float2*)(Out + (size_t)m * 1024 + coln)
                            = make_float2(acc[mi][ni][half * 2 + 0],
                                          acc[mi][ni][half * 2 + 1]);
                    }
                }
            }
        }
    }
}

// ---------------------------------------------------------------------------
// Tensor-core flash attention (tf32 mma.sync): swizzled Q/K (LDS.128 QK^T
// fragments) + row-major V. q-tile 128 rows, k-tile 64 keys, 2-stage
// cp.async, ONE barrier per k-tile. Q pre-scaled by 1/8.
// Epilogue writes g_attn as fp16 with the k-permutation for the out-proj.
// ---------------------------------------------------------------------------
// Smem floats: Qs 128*64 (swizzled), Ks 2*64*64 (swizzled), Vs 2*64*68, PM 2*64
#define ATTN_SM_FLOATS (8192 + 8192 + 8704 + 128)
#define ATTN_SM_BYTES  (ATTN_SM_FLOATS * 4)

__device__ __forceinline__ void stage_kv(
    float* Kdst, float* Vdst, float* PMdst,
    const float* Kg_tile, const float* Vg_tile, const float* Bsrc, int tid)
{
#pragma unroll
    for (int i = 0; i < 4; ++i) {
        int idx = tid + i * 256;
        int row = idx >> 4;          // key row 0..63
        int ch  = idx & 15;          // 16B chunk
        CP16(smem_u32(Kdst + row * 64 + ((ch ^ (row & 7)) << 2)),
             Kg_tile + (size_t)row * 64 + ch * 4);
        CP16(smem_u32(Vdst + row * 68 + ch * 4),
             Vg_tile + (size_t)row * 64 + ch * 4);
    }
    if (tid < 16) CP16(smem_u32(PMdst + tid * 4), Bsrc + tid * 4);
}

__global__ __launch_bounds__(256, 2) void attn_tc()
{
    extern __shared__ float sm[];
    float* Qs = sm;                 // [128][64] swizzled
    float* Ks = Qs + 8192;          // [2][64][64] swizzled
    float* Vs = Ks + 8192;          // [2][64][68]
    float* PM = Vs + 8704;          // [2][64]

    const int qt    = 15 - (int)blockIdx.x;         // heavy tiles first
    const int qbase = qt * 128;
    const int bh = blockIdx.y;
    const int b  = bh >> 4, h = bh & 15;
    const int tid  = threadIdx.x;
    const int warp = tid >> 5, lane = tid & 31;
    const int g = lane >> 2, tg = lane & 3;
    const int nkt = 2 * (qt + 1);

    const float* Kg = g_k + (size_t)bh * S_LEN * HDIM;
    const float* Vg = g_v + (size_t)bh * S_LEN * HDIM;
    const float* Bg = g_bias + b * S_LEN;

    stage_kv(Ks, Vs, PM, Kg, Vg, Bg, tid);
    CP_COMMIT;

    {
        const float* Qg = g_q + ((size_t)bh * S_LEN + qbase) * HDIM;
#pragma unroll
        for (int r = 0; r < 8; ++r) {
            int idx = tid + r * 256;
            int row = idx >> 4, ch = idx & 15;
            *(float4*)&Qs[row * 64 + ((ch ^ (row & 7)) << 2)]
                = *(const float4*)&Qg[row * 64 + ch * 4];
        }
    }

    float S[8][4], O[8][4], mrow[2], lrow[2];
    mrow[0] = mrow[1] = -INFINITY;
    lrow[0] = lrow[1] = 0.0f;
#pragma unroll
    for (int t = 0; t < 8; t++)
#pragma unroll
        for (int j = 0; j < 4; j++) O[t][j] = 0.0f;

    const int wrow0 = qbase + warp * 16;

    for (int kt = 0; kt < nkt; ++kt) {
        const int buf   = kt & 1;
        const int kbase = kt * 64;

        CP_WAIT0;
        __syncthreads();

        if (kt + 1 < nkt) {
            int nb  = buf ^ 1;
            int kb2 = (kt + 1) * 64;
            stage_kv(Ks + nb * 4096, Vs + nb * 4352, PM + nb * 64,
                     Kg + (size_t)kb2 * 64, Vg + (size_t)kb2 * 64, Bg + kb2, tid);
        }
        CP_COMMIT;

        if (kbase <= wrow0 + 15) {     // per-warp causal tile skip
            const float* Kb  = Ks + buf * 4096;
            const float* Vb  = Vs + buf * 4352;
            const float* PMb = PM + buf * 64;

#pragma unroll
            for (int nt = 0; nt < 8; nt++)
#pragma unroll
                for (int j = 0; j < 4; j++) S[nt][j] = 0.0f;

            const int qrow = (warp * 16 + g) * 64;
#pragma unroll
            for (int j = 0; j < 4; ++j) {
                const int sw = (((tg + 4 * j) ^ g) << 2);
                float4 a0 = *(const float4*)&Qs[qrow + sw];
                float4 a1 = *(const float4*)&Qs[qrow + 8 * 64 + sw];
#pragma unroll
                for (int nt = 0; nt < 8; ++nt) {
                    float4 kb = *(const float4*)&Kb[(nt * 8 + g) * 64 + sw];
                    mma_m16n8k8(S[nt], a0.x, a1.x, a0.y, a1.y, kb.x, kb.y);
                    mma_m16n8k8(S[nt], a0.z, a1.z, a0.w, a1.w, kb.z, kb.w);
                }
            }

            float2 pmb[8];
#pragma unroll
            for (int nt = 0; nt < 8; nt++)
                pmb[nt] = *(const float2*)&PMb[nt * 8 + 2 * tg];

            const bool do_causal = (kbase + 63 > wrow0);

            {
                int row_lo = wrow0 + g;
                int row_hi = row_lo + 8;
                float mx_lo = -INFINITY, mx_hi = -INFINITY;
#pragma unroll
                for (int nt = 0; nt < 8; nt++) {
                    int col0 = kbase + nt * 8 + 2 * tg;
                    float v0 = S[nt][0] + pmb[nt].x;
                    float v1 = S[nt][1] + pmb[nt].y;
                    float v2 = S[nt][2] + pmb[nt].x;
                    float v3 = S[nt][3] + pmb[nt].y;
                    if (do_causal) {
                        if (col0     > row_lo) v0 = -1e30f;
                        if (col0 + 1 > row_lo) v1 = -1e30f;
                        if (col0     > row_hi) v2 = -1e30f;
                        if (col0 + 1 > row_hi) v3 = -1e30f;
                    }
                    S[nt][0] = v0; S[nt][1] = v1;
                    S[nt][2] = v2; S[nt][3] = v3;
                    mx_lo = fmaxf(mx_lo, fmaxf(v0, v1));
                    mx_hi = fmaxf(mx_hi, fmaxf(v2, v3));
                }
                mx_lo = fmaxf(mx_lo, __shfl_xor_sync(0xffffffffu, mx_lo, 1));
                mx_lo = fmaxf(mx_lo, __shfl_xor_sync(0xffffffffu, mx_lo, 2));
                mx_hi = fmaxf(mx_hi, __shfl_xor_sync(0xffffffffu, mx_hi, 1));
                mx_hi = fmaxf(mx_hi, __shfl_xor_sync(0xffffffffu, mx_hi, 2));

                float mn_lo = fmaxf(mrow[0], mx_lo);
                float mn_hi = fmaxf(mrow[1], mx_hi);
                float al_lo = __expf(mrow[0] - mn_lo);
                float al_hi = __expf(mrow[1] - mn_hi);

                float s_lo = 0.0f, s_hi = 0.0f;
#pragma unroll
                for (int nt = 0; nt < 8; nt++) {
                    float p0 = __expf(S[nt][0] - mn_lo);
                    float p1 = __expf(S[nt][1] - mn_lo);
                    float p2 = __expf(S[nt][2] - mn_hi);
                    float p3 = __expf(S[nt][3] - mn_hi);
                    s_lo += p0 + p1;
                    s_hi += p2 + p3;
                    S[nt][0] = to_tf32(p0);
                    S[nt][1] = to_tf32(p1);
                    S[nt][2] = to_tf32(p2);
                    S[nt][3] = to_tf32(p3);
                }
                s_lo += __shfl_xor_sync(0xffffffffu, s_lo, 1);
                s_lo += __shfl_xor_sync(0xffffffffu, s_lo, 2);
                s_hi += __shfl_xor_sync(0xffffffffu, s_hi, 1);
                s_hi += __shfl_xor_sync(0xffffffffu, s_hi, 2);

                lrow[0] = lrow[0] * al_lo + s_lo;
                lrow[1] = lrow[1] * al_hi + s_hi;
                mrow[0] = mn_lo;
                mrow[1] = mn_hi;
#pragma unroll
                for (int hd = 0; hd < 8; hd++) {
                    O[hd][0] *= al_lo;
                    O[hd][1] *= al_lo;
                    O[hd][2] *= al_hi;
                    O[hd][3] *= al_hi;
                }
            }

#pragma unroll
            for (int ks = 0; ks < 8; ++ks) {
#pragma unroll
                for (int hd = 0; hd < 8; ++hd) {
                    float b0 = Vb[(ks * 8 + 2 * tg    ) * 68 + hd * 8 + g];
                    float b1 = Vb[(ks * 8 + 2 * tg + 1) * 68 + hd * 8 + g];
                    mma_m16n8k8(O[hd], S[ks][0], S[ks][2],
                                       S[ks][1], S[ks][3], b0, b1);
                }
            }
        }
    }

    // epilogue: normalize + write g_attn as fp16 at PERMUTED k positions.
    // logical col c = h*64 + hd*8 + 2tg -> block base h*64 + (hd>>2)*32,
    // local l = (hd&3)*8 + 2tg -> phys = 8*tg + 2*(hd&3).
    {
        float inv_lo = 1.0f / lrow[0];
        float inv_hi = 1.0f / lrow[1];
        int row_lo = wrow0 + g;
#pragma unroll
        for (int hd = 0; hd < 8; hd++) {
            int pcol = h * 64 + (hd >> 2) * 32 + 8 * tg + 2 * (hd & 3);
            *(__half2*)(g_attn + ((size_t)b * S_LEN + row_lo) * D_MODEL + pcol) =
                __float22half2_rn(make_float2(O[hd][0] * inv_lo, O[hd][1] * inv_lo));
            *(__half2*)(g_attn + ((size_t)b * S_LEN + row_lo + 8) * D_MODEL + pcol) =
                __float22half2_rn(make_float2(O[hd][2] * inv_hi, O[hd][3] * inv_hi));
        }
    }
}

// ---------------------------------------------------------------------------
extern "C" void kernel_launch(void* const* d_in, const int* in_sizes, int n_in,
                              void* d_out, int out_size)
{
    const float* x      = (const float*)d_in[0];
    const int*   pmask  = (const int*)d_in[1];
    const float* w_qkv  = (const float*)d_in[2];
    const float* w_o    = (const float*)d_in[3];
    float*       out    = (float*)d_out;

    cudaFuncSetAttribute(attn_tc,
                         cudaFuncAttributeMaxDynamicSharedMemorySize, ATTN_SM_BYTES);
    cudaFuncSetAttribute(mm_fp16<0>,
                         cudaFuncAttributeMaxDynamicSharedMemorySize, MMH_SM_BYTES);
    cudaFuncSetAttribute(mm_fp16<1>,
                         cudaFuncAttributeMaxDynamicSharedMemorySize, MMH_SM_BYTES);

    __half *xc, *wc, *woc, *attn_ptr;
    cudaGetSymbolAddress((void**)&xc, g_xc);
    cudaGetSymbolAddress((void**)&wc, g_wc);
    cudaGetSymbolAddress((void**)&woc, g_woc);
    cudaGetSymbolAddress((void**)&attn_ptr, g_attn);

    rope_table_kernel<<<(S_LEN * 32 + 255) / 256, 256>>>();
    cvt_all_kernel<<<(N2_X + N2_W + N2_WO + 255) / 256, 256>>>(
        (const float2*)x, (const float2*)w_qkv, (const float2*)w_o);
    bias_kernel<<<(BATCH * S_LEN + 255) / 256, 256>>>(pmask);

    // QKV projection + RoPE: M=8192, N=3072 (CTA 128x128, 8 warps, fp16 TC)
    mm_fp16<0><<<dim3(3 * D_MODEL / 128, (BATCH * S_LEN) / 128), 256, MMH_SM_BYTES>>>(xc, wc, nullptr);
    // Flash attention (tf32 mma.sync)
    attn_tc<<<dim3(16, BH), 256, ATTN_SM_BYTES>>>();
    // Output projection: M=8192, N=1024
    mm_fp16<1><<<dim3(D_MODEL / 128, (BATCH * S_LEN) / 128), 256, MMH_SM_BYTES>>>(attn_ptr, woc, out);
}

// round 14
// speedup vs baseline: 1.8894x; 1.3110x over previous
#include <cuda_runtime.h>
#include <cuda_fp16.h>
#include <math.h>
#include <stdint.h>

// Problem constants
#define S_LEN   2048
#define D_MODEL 1024
#define NHEAD   16
#define HDIM    64
#define BATCH   4
#define BH      (BATCH * NHEAD)   // 64

// Scratch (device globals — no allocation allowed)
__device__ __half g_q[(size_t)BH * S_LEN * HDIM];          // fp16, kperm'd over d, pre-scaled 1/8
__device__ __half g_k[(size_t)BH * S_LEN * HDIM];          // fp16, kperm'd over d
__device__ __half g_v[(size_t)BH * S_LEN * HDIM];          // fp16, row-major
__device__ __half g_attn[(size_t)BATCH * S_LEN * D_MODEL]; // fp16, kperm'd (out-proj A)
__device__ float  g_cos[S_LEN * (HDIM / 2)];
__device__ float  g_sin[S_LEN * (HDIM / 2)];
__device__ __half g_xc[(size_t)BATCH * S_LEN * D_MODEL];   // fp16, kperm'd
__device__ __half g_wc[(size_t)3 * D_MODEL * D_MODEL];     // fp16, kperm'd
__device__ __half g_woc[(size_t)D_MODEL * D_MODEL];        // fp16, kperm'd
__device__ float  g_bias[BATCH * S_LEN];                   // 0 or -1e30 padding bias

// ---------------------------------------------------------------------------
// helpers
// ---------------------------------------------------------------------------
__device__ __forceinline__ uint32_t pack_h2(float a, float b) {
    __half2 h = __float22half2_rn(make_float2(a, b));
    return *reinterpret_cast<uint32_t*>(&h);
}

// fp16 m16n8k16, fp32 accum
__device__ __forceinline__ void mma_fp16(
    float* c, uint32_t a0, uint32_t a1, uint32_t a2, uint32_t a3,
    uint32_t b0, uint32_t b1)
{
    asm volatile(
        "mma.sync.aligned.m16n8k16.row.col.f32.f16.f16.f32 "
        "{%0,%1,%2,%3}, {%4,%5,%6,%7}, {%8,%9}, {%0,%1,%2,%3};"
        : "+f"(c[0]), "+f"(c[1]), "+f"(c[2]), "+f"(c[3])
        : "r"(a0), "r"(a1), "r"(a2), "r"(a3), "r"(b0), "r"(b1));
}

__device__ __forceinline__ uint32_t smem_u32(const void* p) {
    return (uint32_t)__cvta_generic_to_shared(p);
}
#define CP16(d, s)  asm volatile("cp.async.ca.shared.global [%0], [%1], 16;" :: "r"(d), "l"(s))
#define CP_COMMIT   asm volatile("cp.async.commit_group;")
#define CP_WAIT0    asm volatile("cp.async.wait_group 0;")
#define CP_WAIT1    asm volatile("cp.async.wait_group 1;")

#define LDSM_X4_T(r0, r1, r2, r3, addr)                                        \
    asm volatile("ldmatrix.sync.aligned.m8n8.x4.trans.shared.b16 "             \
                 "{%0,%1,%2,%3}, [%4];"                                        \
                 : "=r"(r0), "=r"(r1), "=r"(r2), "=r"(r3) : "r"(addr))

// k-permutation within 32-blocks: phys(l) = 8*((l>>1)&3) + 2*(l>>3) + (l&1).
__device__ __forceinline__ uint32_t kperm32(uint32_t l) {
    return 8u * ((l >> 1) & 3u) + 2u * (l >> 3) + (l & 1u);
}

// ---------------------------------------------------------------------------
// prep kernels
// ---------------------------------------------------------------------------
__global__ void rope_table_kernel() {
    int idx = blockIdx.x * blockDim.x + threadIdx.x;
    if (idx >= S_LEN * (HDIM / 2)) return;
    int s = idx >> 5;
    int i = idx & 31;
    float inv = exp2f(-13.287712379549449f * (2.0f * (float)i / 64.0f));
    float ang = (float)s * inv;
    float sn, cs;
    sincosf(ang, &sn, &cs);
    g_cos[idx] = cs;
    g_sin[idx] = sn;
}

#define N2_X  4194304u
#define N2_W  1572864u
#define N2_WO 524288u
__global__ void cvt_all_kernel(const float2* __restrict__ x,
                               const float2* __restrict__ w,
                               const float2* __restrict__ wo) {
    uint32_t i = blockIdx.x * blockDim.x + threadIdx.x;
    const float2* src;
    __half* dst;
    size_t e;
    if (i < N2_X)                  { src = x  + i;                  dst = g_xc;  e = (size_t)i * 2; }
    else if (i < N2_X + N2_W)      { src = w  + (i - N2_X);         dst = g_wc;  e = (size_t)(i - N2_X) * 2; }
    else if (i < N2_X + N2_W + N2_WO) { src = wo + (i - N2_X - N2_W); dst = g_woc; e = (size_t)(i - N2_X - N2_W) * 2; }
    else return;
    float2 v = *src;
    size_t pos = (e & ~(size_t)31) + kperm32((uint32_t)(e & 31));
    *(__half2*)(dst + pos) = __float22half2_rn(v);
}

__global__ void bias_kernel(const int* __restrict__ pmask) {
    int i = blockIdx.x * blockDim.x + threadIdx.x;
    if (i < BATCH * S_LEN)
        g_bias[i] = (pmask[i] == 0) ? -1e30f : 0.0f;
}

// ---------------------------------------------------------------------------
// fp16 tensor-core GEMM (unchanged structure from round 13):
// CTA 128x128, 8 warps (2m x 4n), warp tile 64x32, BK=32, 3-stage ring.
// MODE 0 epilogue: q/k -> RoPE (+1/8 q) -> fp16 kperm'd; v -> fp16 row-major.
// MODE 1: fp32 store to Out.
// ---------------------------------------------------------------------------
#define MMH_STAGE_BYTES 8192
#define MMH_SM_BYTES    (6 * MMH_STAGE_BYTES)   // 48KB

__device__ __forceinline__ void mmh_stage(
    uint32_t sA, uint32_t sB, const __half* Ag, const __half* Bg, int tid)
{
#pragma unroll
    for (int i = 0; i < 2; ++i) {
        int idx = tid + i * 256;
        int r   = idx >> 2;
        int ch  = idx & 3;
        uint32_t so = (uint32_t)(r * 64 + ((ch ^ (r & 3)) << 4));
        CP16(sA + so, Ag + (size_t)r * 1024 + ch * 8);
        CP16(sB + so, Bg + (size_t)r * 1024 + ch * 8);
    }
}

template<int MODE>
__global__ __launch_bounds__(256, 2) void mm_fp16(
    const __half* __restrict__ A, const __half* __restrict__ Bw,
    float* __restrict__ Out)
{
    extern __shared__ __half smh[];

    const int tid    = threadIdx.x;
    const int m_base = blockIdx.y * 128;
    const int n_base = blockIdx.x * 128;

    const __half* Ag = A  + (size_t)m_base * 1024;
    const __half* Bg = Bw + (size_t)n_base * 1024;

    const int warp = tid >> 5;
    const int lane = tid & 31;
    const int wm = warp & 1;
    const int wn = warp >> 1;
    const int g  = lane >> 2;
    const int tg = lane & 3;

    float acc[4][4][4];
#pragma unroll
    for (int mi = 0; mi < 4; mi++)
#pragma unroll
        for (int ni = 0; ni < 4; ni++)
#pragma unroll
            for (int j = 0; j < 4; j++) acc[mi][ni][j] = 0.0f;

    const uint32_t sb = smem_u32(smh);
#pragma unroll
    for (int p = 0; p < 2; ++p) {
        mmh_stage(sb + p * MMH_STAGE_BYTES,
                  sb + 3 * MMH_STAGE_BYTES + p * MMH_STAGE_BYTES,
                  Ag + p * 32, Bg + p * 32, tid);
        CP_COMMIT;
    }

    int sidx = 0;
    for (int kt = 0; kt < 32; ++kt) {
        CP_WAIT1;
        __syncthreads();

        {
            int ps = sidx + 2; if (ps >= 3) ps -= 3;
            if (kt + 2 < 32)
                mmh_stage(sb + ps * MMH_STAGE_BYTES,
                          sb + 3 * MMH_STAGE_BYTES + ps * MMH_STAGE_BYTES,
                          Ag + (kt + 2) * 32, Bg + (kt + 2) * 32, tid);
            CP_COMMIT;
        }

        const __half* Asb = smh + sidx * 4096;
        const __half* Bsb = smh + 12288 + sidx * 4096;

        uint4 af[4][2], bf[4];
#pragma unroll
        for (int mi = 0; mi < 4; mi++) {
            int r0 = wm * 64 + mi * 16 + g;
            af[mi][0] = *(const uint4*)&Asb[r0 * 32 + ((tg ^ (r0 & 3)) << 3)];
            int r1 = r0 + 8;
            af[mi][1] = *(const uint4*)&Asb[r1 * 32 + ((tg ^ (r1 & 3)) << 3)];
        }
#pragma unroll
        for (int ni = 0; ni < 4; ni++) {
            int rb = wn * 32 + ni * 8 + g;
            bf[ni] = *(const uint4*)&Bsb[rb * 32 + ((tg ^ (rb & 3)) << 3)];
        }
#pragma unroll
        for (int mi = 0; mi < 4; mi++)
#pragma unroll
            for (int ni = 0; ni < 4; ni++) {
                mma_fp16(acc[mi][ni],
                         af[mi][0].x, af[mi][1].x, af[mi][0].y, af[mi][1].y,
                         bf[ni].x, bf[ni].y);
                mma_fp16(acc[mi][ni],
                         af[mi][0].z, af[mi][1].z, af[mi][0].w, af[mi][1].w,
                         bf[ni].z, bf[ni].w);
            }
        if (++sidx == 3) sidx = 0;
    }

    {
        const int n0    = n_base + wn * 32;
        const int part  = n0 >> 10;
        const int h     = (n0 & 1023) >> 6;
        const int dbase = n0 & 63;          // 0 or 32
#pragma unroll
        for (int mi = 0; mi < 4; mi++) {
            int row0 = m_base + wm * 64 + mi * 16 + g;
#pragma unroll
            for (int ni = 0; ni < 4; ni++) {
                if (MODE == 0) {
                    int d0 = dbase + ni * 8 + 2 * tg;
                    int i0 = d0 >> 1;
#pragma unroll
                    for (int half = 0; half < 2; half++) {
                        int m = row0 + half * 8;
                        int b = m >> 11, s = m & 2047;
                        float v0 = acc[mi][ni][half * 2 + 0];
                        float v1 = acc[mi][ni][half * 2 + 1];
                        size_t rowoff = ((size_t)(b * NHEAD + h) * S_LEN + s) * HDIM;
                        if (part == 2) {
                            *(__half2*)(g_v + rowoff + d0) =
                                __float22half2_rn(make_float2(v0, v1));
                        } else {
                            float cs = g_cos[s * 32 + i0], sn = g_sin[s * 32 + i0];
                            float r0 = v0 * cs - v1 * sn;
                            float r1 = v0 * sn + v1 * cs;
                            if (part == 0) { r0 *= 0.125f; r1 *= 0.125f; }
                            // kperm'd position: block dbase + phys(8tg + 2ni)
                            int pcol = (dbase & 32) + 8 * tg + 2 * ni;
                            __half* dsth = (part == 0) ? g_q : g_k;
                            *(__half2*)(dsth + rowoff + pcol) =
                                __float22half2_rn(make_float2(r0, r1));
                        }
                    }
                } else {
                    int coln = n0 + ni * 8 + 2 * tg;
#pragma unroll
                    for (int half = 0; half < 2; half++) {
                        int m = row0 + half * 8;
                        *(float2*)(Out + (size_t)m * 1024 + coln)
                            = make_float2(acc[mi][ni][half * 2 + 0],
                                          acc[mi][ni][half * 2 + 1]);
                    }
                }
            }
        }
    }
}

// ---------------------------------------------------------------------------
// fp16 tensor-core flash attention (m16n8k16).
// q-tile 128 rows, k-tile 64 keys, 2-stage cp.async, ONE barrier per k-tile.
// Q/K fp16 kperm'd (uint4 fragment loads, swizzle ch^(row&7) over 128B rows);
// V fp16 row-major pad-72-half rows, B-fragments via ldmatrix.x4.trans.
// Q pre-scaled by 1/8. Epilogue -> g_attn fp16 kperm'd.
// ---------------------------------------------------------------------------
// smem bytes: Qs 16384 | Ks 2x8192 | Vs 2x9216 | PM 2x256  = 51712
#define ATTN_QS   0
#define ATTN_KS   16384
#define ATTN_VS   32768
#define ATTN_PM   51200
#define ATTN_SM_BYTES 51712

__device__ __forceinline__ void stage_kv_h(
    uint32_t kdst, uint32_t vdst, uint32_t pmdst,
    const __half* Kg, const __half* Vg, const float* Bsrc, int tid)
{
#pragma unroll
    for (int i = 0; i < 2; ++i) {
        int idx = tid + i * 256;       // 0..511
        int row = idx >> 3;            // key 0..63
        int ch  = idx & 7;             // 16B chunk
        CP16(kdst + row * 128 + ((ch ^ (row & 7)) << 4), Kg + (size_t)row * 64 + ch * 8);
        CP16(vdst + row * 144 + (ch << 4),               Vg + (size_t)row * 64 + ch * 8);
    }
    if (tid < 16) CP16(pmdst + tid * 16, Bsrc + tid * 4);
}

__global__ __launch_bounds__(256, 2) void attn_tc()
{
    extern __shared__ char smc[];
    const uint32_t base = smem_u32(smc);
    float* PMf = (float*)(smc + ATTN_PM);

    const int qt    = 15 - (int)blockIdx.x;         // heavy tiles first
    const int qbase = qt * 128;
    const int bh = blockIdx.y;
    const int b  = bh >> 4, h = bh & 15;
    const int tid  = threadIdx.x;
    const int warp = tid >> 5, lane = tid & 31;
    const int g = lane >> 2, tg = lane & 3;
    const int nkt = 2 * (qt + 1);

    const __half* Qg = g_q + ((size_t)bh * S_LEN + qbase) * HDIM;
    const __half* Kg = g_k + (size_t)bh * S_LEN * HDIM;
    const __half* Vg = g_v + (size_t)bh * S_LEN * HDIM;
    const float*  Bg = g_bias + b * S_LEN;

    stage_kv_h(base + ATTN_KS, base + ATTN_VS, base + ATTN_PM, Kg, Vg, Bg, tid);
    CP_COMMIT;

    // stage Q [128 rows x 128B], swizzle ch^(row&7)
#pragma unroll
    for (int r = 0; r < 4; ++r) {
        int idx = tid + r * 256;
        int row = idx >> 3, ch = idx & 7;
        *(uint4*)(smc + ATTN_QS + row * 128 + ((ch ^ (row & 7)) << 4))
            = *(const uint4*)(Qg + (size_t)row * 64 + ch * 8);
    }

    float S[8][4], O[8][4], mrow[2], lrow[2];
    mrow[0] = mrow[1] = -INFINITY;
    lrow[0] = lrow[1] = 0.0f;
#pragma unroll
    for (int t = 0; t < 8; t++)
#pragma unroll
        for (int j = 0; j < 4; j++) O[t][j] = 0.0f;

    const int wrow0 = qbase + warp * 16;
    const int qr0 = warp * 16 + g;          // local q row
    const int kl  = lane & 15;              // ldmatrix key lane
    const int dh  = lane >> 4;              // ldmatrix d-half (0/1)

    for (int kt = 0; kt < nkt; ++kt) {
        const int buf   = kt & 1;
        const int kbase = kt * 64;

        CP_WAIT0;
        __syncthreads();

        if (kt + 1 < nkt) {
            int nb  = buf ^ 1;
            int kb2 = (kt + 1) * 64;
            stage_kv_h(base + ATTN_KS + nb * 8192, base + ATTN_VS + nb * 9216,
                       base + ATTN_PM + nb * 256,
                       Kg + (size_t)kb2 * 64, Vg + (size_t)kb2 * 64, Bg + kb2, tid);
        }
        CP_COMMIT;

        if (kbase <= wrow0 + 15) {     // per-warp causal tile skip
            const char* Kb = smc + ATTN_KS + buf * 8192;
            const float* PMb = PMf + buf * 64;

            // ---- S = Q K^T (fp16 m16n8k16, q pre-scaled by 1/8)
#pragma unroll
            for (int nt = 0; nt < 8; nt++)
#pragma unroll
                for (int j = 0; j < 4; j++) S[nt][j] = 0.0f;

#pragma unroll
            for (int blk = 0; blk < 2; ++blk) {
                const int c = blk * 4 + tg;
                uint4 af0 = *(const uint4*)(smc + ATTN_QS + qr0 * 128 + ((c ^ (qr0 & 7)) << 4));
                uint4 af1 = *(const uint4*)(smc + ATTN_QS + (qr0 + 8) * 128 + ((c ^ (qr0 & 7)) << 4));
#pragma unroll
                for (int nt = 0; nt < 8; ++nt) {
                    int krow = nt * 8 + g;
                    uint4 bf = *(const uint4*)(Kb + krow * 128 + ((c ^ g) << 4));
                    mma_fp16(S[nt], af0.x, af1.x, af0.y, af1.y, bf.x, bf.y);
                    mma_fp16(S[nt], af0.z, af1.z, af0.w, af1.w, bf.z, bf.w);
                }
            }

            // ---- mask + online softmax -> packed fp16 P fragments
            float2 pmb[8];
#pragma unroll
            for (int nt = 0; nt < 8; nt++)
                pmb[nt] = *(const float2*)&PMb[nt * 8 + 2 * tg];

            const bool do_causal = (kbase + 63 > wrow0);
            uint32_t pa_lo[8], pa_hi[8];

            {
                int row_lo = wrow0 + g;
                int row_hi = row_lo + 8;
                float mx_lo = -INFINITY, mx_hi = -INFINITY;
#pragma unroll
                for (int nt = 0; nt < 8; nt++) {
                    int col0 = kbase + nt * 8 + 2 * tg;
                    float v0 = S[nt][0] + pmb[nt].x;
                    float v1 = S[nt][1] + pmb[nt].y;
                    float v2 = S[nt][2] + pmb[nt].x;
                    float v3 = S[nt][3] + pmb[nt].y;
                    if (do_causal) {
                        if (col0     > row_lo) v0 = -1e30f;
                        if (col0 + 1 > row_lo) v1 = -1e30f;
                        if (col0     > row_hi) v2 = -1e30f;
                        if (col0 + 1 > row_hi) v3 = -1e30f;
                    }
                    S[nt][0] = v0; S[nt][1] = v1;
                    S[nt][2] = v2; S[nt][3] = v3;
                    mx_lo = fmaxf(mx_lo, fmaxf(v0, v1));
                    mx_hi = fmaxf(mx_hi, fmaxf(v2, v3));
                }
                mx_lo = fmaxf(mx_lo, __shfl_xor_sync(0xffffffffu, mx_lo, 1));
                mx_lo = fmaxf(mx_lo, __shfl_xor_sync(0xffffffffu, mx_lo, 2));
                mx_hi = fmaxf(mx_hi, __shfl_xor_sync(0xffffffffu, mx_hi, 1));
                mx_hi = fmaxf(mx_hi, __shfl_xor_sync(0xffffffffu, mx_hi, 2));

                float mn_lo = fmaxf(mrow[0], mx_lo);
                float mn_hi = fmaxf(mrow[1], mx_hi);
                float al_lo = __expf(mrow[0] - mn_lo);
                float al_hi = __expf(mrow[1] - mn_hi);

                float s_lo = 0.0f, s_hi = 0.0f;
#pragma unroll
                for (int nt = 0; nt < 8; nt++) {
                    float p0 = __expf(S[nt][0] - mn_lo);
                    float p1 = __expf(S[nt][1] - mn_lo);
                    float p2 = __expf(S[nt][2] - mn_hi);
                    float p3 = __expf(S[nt][3] - mn_hi);
                    s_lo += p0 + p1;
                    s_hi += p2 + p3;
                    pa_lo[nt] = pack_h2(p0, p1);
                    pa_hi[nt] = pack_h2(p2, p3);
                }
                s_lo += __shfl_xor_sync(0xffffffffu, s_lo, 1);
                s_lo += __shfl_xor_sync(0xffffffffu, s_lo, 2);
                s_hi += __shfl_xor_sync(0xffffffffu, s_hi, 1);
                s_hi += __shfl_xor_sync(0xffffffffu, s_hi, 2);

                lrow[0] = lrow[0] * al_lo + s_lo;
                lrow[1] = lrow[1] * al_hi + s_hi;
                mrow[0] = mn_lo;
                mrow[1] = mn_hi;
#pragma unroll
                for (int hd = 0; hd < 8; hd++) {
                    O[hd][0] *= al_lo;
                    O[hd][1] *= al_lo;
                    O[hd][2] *= al_hi;
                    O[hd][3] *= al_hi;
                }
            }

            // ---- O += P V  (fp16 m16n8k16; V B-frags via ldmatrix.x4.trans)
            const uint32_t vb = base + ATTN_VS + buf * 9216;
#pragma unroll
            for (int kb = 0; kb < 4; ++kb) {
                uint32_t a0 = pa_lo[2 * kb],     a1 = pa_hi[2 * kb];
                uint32_t a2 = pa_lo[2 * kb + 1], a3 = pa_hi[2 * kb + 1];
#pragma unroll
                for (int dp = 0; dp < 4; ++dp) {
                    uint32_t addr = vb + (kb * 16 + kl) * 144 + dp * 32 + dh * 16;
                    uint32_t r0, r1, r2, r3;
                    LDSM_X4_T(r0, r1, r2, r3, addr);
                    mma_fp16(O[2 * dp],     a0, a1, a2, a3, r0, r1);
                    mma_fp16(O[2 * dp + 1], a0, a1, a2, a3, r2, r3);
                }
            }
        }
    }

    // epilogue: normalize + write g_attn fp16 at permuted k positions.
    {
        float inv_lo = 1.0f / lrow[0];
        float inv_hi = 1.0f / lrow[1];
        int row_lo = wrow0 + g;
#pragma unroll
        for (int hd = 0; hd < 8; hd++) {
            int pcol = h * 64 + (hd >> 2) * 32 + 8 * tg + 2 * (hd & 3);
            *(__half2*)(g_attn + ((size_t)b * S_LEN + row_lo) * D_MODEL + pcol) =
                __float22half2_rn(make_float2(O[hd][0] * inv_lo, O[hd][1] * inv_lo));
            *(__half2*)(g_attn + ((size_t)b * S_LEN + row_lo + 8) * D_MODEL + pcol) =
                __float22half2_rn(make_float2(O[hd][2] * inv_hi, O[hd][3] * inv_hi));
        }
    }
}

// ---------------------------------------------------------------------------
extern "C" void kernel_launch(void* const* d_in, const int* in_sizes, int n_in,
                              void* d_out, int out_size)
{
    const float* x      = (const float*)d_in[0];
    const int*   pmask  = (const int*)d_in[1];
    const float* w_qkv  = (const float*)d_in[2];
    const float* w_o    = (const float*)d_in[3];
    float*       out    = (float*)d_out;

    cudaFuncSetAttribute(attn_tc,
                         cudaFuncAttributeMaxDynamicSharedMemorySize, ATTN_SM_BYTES);
    cudaFuncSetAttribute(mm_fp16<0>,
                         cudaFuncAttributeMaxDynamicSharedMemorySize, MMH_SM_BYTES);
    cudaFuncSetAttribute(mm_fp16<1>,
                         cudaFuncAttributeMaxDynamicSharedMemorySize, MMH_SM_BYTES);

    __half *xc, *wc, *woc, *attn_ptr;
    cudaGetSymbolAddress((void**)&xc, g_xc);
    cudaGetSymbolAddress((void**)&wc, g_wc);
    cudaGetSymbolAddress((void**)&woc, g_woc);
    cudaGetSymbolAddress((void**)&attn_ptr, g_attn);

    rope_table_kernel<<<(S_LEN * 32 + 255) / 256, 256>>>();
    cvt_all_kernel<<<(N2_X + N2_W + N2_WO + 255) / 256, 256>>>(
        (const float2*)x, (const float2*)w_qkv, (const float2*)w_o);
    bias_kernel<<<(BATCH * S_LEN + 255) / 256, 256>>>(pmask);

    // QKV projection + RoPE: M=8192, N=3072 (fp16 TC)
    mm_fp16<0><<<dim3(3 * D_MODEL / 128, (BATCH * S_LEN) / 128), 256, MMH_SM_BYTES>>>(xc, wc, nullptr);
    // Flash attention (fp16 m16n8k16)
    attn_tc<<<dim3(16, BH), 256, ATTN_SM_BYTES>>>();
    // Output projection: M=8192, N=1024
    mm_fp16<1><<<dim3(D_MODEL / 128, (BATCH * S_LEN) / 128), 256, MMH_SM_BYTES>>>(attn_ptr, woc, out);
}

// round 15
// speedup vs baseline: 1.9850x; 1.0506x over previous
#include <cuda_runtime.h>
#include <cuda_fp16.h>
#include <math.h>
#include <stdint.h>

// Problem constants
#define S_LEN   2048
#define D_MODEL 1024
#define NHEAD   16
#define HDIM    64
#define BATCH   4
#define BH      (BATCH * NHEAD)   // 64

// Scratch (device globals — no allocation allowed)
__device__ __half g_q[(size_t)BH * S_LEN * HDIM];          // fp16, kperm'd over d, pre-scaled 1/8
__device__ __half g_k[(size_t)BH * S_LEN * HDIM];          // fp16, kperm'd over d
__device__ __half g_v[(size_t)BH * S_LEN * HDIM];          // fp16, row-major
__device__ __half g_attn[(size_t)BATCH * S_LEN * D_MODEL]; // fp16, kperm'd (out-proj A)
__device__ float  g_cos[S_LEN * (HDIM / 2)];
__device__ float  g_sin[S_LEN * (HDIM / 2)];
__device__ __half g_xc[(size_t)BATCH * S_LEN * D_MODEL];   // fp16, kperm'd
__device__ __half g_wc[(size_t)3 * D_MODEL * D_MODEL];     // fp16, kperm'd
__device__ __half g_woc[(size_t)D_MODEL * D_MODEL];        // fp16, kperm'd
__device__ float  g_bias[BATCH * S_LEN];                   // 0 or -1e30 padding bias

// ---------------------------------------------------------------------------
// helpers
// ---------------------------------------------------------------------------
__device__ __forceinline__ uint32_t pack_h2(float a, float b) {
    __half2 h = __float22half2_rn(make_float2(a, b));
    return *reinterpret_cast<uint32_t*>(&h);
}

// fp16 m16n8k16, fp32 accum
__device__ __forceinline__ void mma_fp16(
    float* c, uint32_t a0, uint32_t a1, uint32_t a2, uint32_t a3,
    uint32_t b0, uint32_t b1)
{
    asm volatile(
        "mma.sync.aligned.m16n8k16.row.col.f32.f16.f16.f32 "
        "{%0,%1,%2,%3}, {%4,%5,%6,%7}, {%8,%9}, {%0,%1,%2,%3};"
        : "+f"(c[0]), "+f"(c[1]), "+f"(c[2]), "+f"(c[3])
        : "r"(a0), "r"(a1), "r"(a2), "r"(a3), "r"(b0), "r"(b1));
}

__device__ __forceinline__ uint32_t smem_u32(const void* p) {
    return (uint32_t)__cvta_generic_to_shared(p);
}
#define CP16(d, s)  asm volatile("cp.async.ca.shared.global [%0], [%1], 16;" :: "r"(d), "l"(s))
#define CP_COMMIT   asm volatile("cp.async.commit_group;")
#define CP_WAIT0    asm volatile("cp.async.wait_group 0;")
#define CP_WAIT1    asm volatile("cp.async.wait_group 1;")

#define LDSM_X4_T(r0, r1, r2, r3, addr)                                        \
    asm volatile("ldmatrix.sync.aligned.m8n8.x4.trans.shared.b16 "             \
                 "{%0,%1,%2,%3}, [%4];"                                        \
                 : "=r"(r0), "=r"(r1), "=r"(r2), "=r"(r3) : "r"(addr))

// k-permutation within 32-blocks: phys(l) = 8*((l>>1)&3) + 2*(l>>3) + (l&1).
__device__ __forceinline__ uint32_t kperm32(uint32_t l) {
    return 8u * ((l >> 1) & 3u) + 2u * (l >> 3) + (l & 1u);
}

// ---------------------------------------------------------------------------
// prep kernels
// ---------------------------------------------------------------------------
__global__ void rope_table_kernel() {
    int idx = blockIdx.x * blockDim.x + threadIdx.x;
    if (idx >= S_LEN * (HDIM / 2)) return;
    int s = idx >> 5;
    int i = idx & 31;
    float inv = exp2f(-13.287712379549449f * (2.0f * (float)i / 64.0f));
    float ang = (float)s * inv;
    float sn, cs;
    sincosf(ang, &sn, &cs);
    g_cos[idx] = cs;
    g_sin[idx] = sn;
}

#define N2_X  4194304u
#define N2_W  1572864u
#define N2_WO 524288u
__global__ void cvt_all_kernel(const float2* __restrict__ x,
                               const float2* __restrict__ w,
                               const float2* __restrict__ wo) {
    uint32_t i = blockIdx.x * blockDim.x + threadIdx.x;
    const float2* src;
    __half* dst;
    size_t e;
    if (i < N2_X)                  { src = x  + i;                  dst = g_xc;  e = (size_t)i * 2; }
    else if (i < N2_X + N2_W)      { src = w  + (i - N2_X);         dst = g_wc;  e = (size_t)(i - N2_X) * 2; }
    else if (i < N2_X + N2_W + N2_WO) { src = wo + (i - N2_X - N2_W); dst = g_woc; e = (size_t)(i - N2_X - N2_W) * 2; }
    else return;
    float2 v = *src;
    size_t pos = (e & ~(size_t)31) + kperm32((uint32_t)(e & 31));
    *(__half2*)(dst + pos) = __float22half2_rn(v);
}

__global__ void bias_kernel(const int* __restrict__ pmask) {
    int i = blockIdx.x * blockDim.x + threadIdx.x;
    if (i < BATCH * S_LEN)
        g_bias[i] = (pmask[i] == 0) ? -1e30f : 0.0f;
}

// ---------------------------------------------------------------------------
// fp16 tensor-core GEMM: C[m,n] = sum_k A[m,k] * Bw[n,k]   (K = 1024)
// CTA 128x128, 128 threads = 4 warps, warp grid 2(m) x 2(n), warp tile 64x64
// (crossbar:tensor = 375:512 -> tensor-dominant). BK=32, 3-stage cp.async
// ring, ONE barrier/tile. Operands kperm'd fp16 in gmem; LDS.128 per fragment
// pair per k32.
// MODE 0 epilogue: q/k -> RoPE (+1/8 q) -> fp16 kperm'd; v -> fp16 row-major.
// MODE 1: fp32 store to Out.
// ---------------------------------------------------------------------------
#define MMH_STAGE_BYTES 8192
#define MMH_SM_BYTES    (6 * MMH_STAGE_BYTES)   // 48KB

__device__ __forceinline__ void mmh_stage(
    uint32_t sA, uint32_t sB, const __half* Ag, const __half* Bg, int tid)
{
#pragma unroll
    for (int i = 0; i < 4; ++i) {
        int idx = tid + i * 128;      // 0..511
        int r   = idx >> 2;           // row 0..127
        int ch  = idx & 3;            // 16B chunk
        uint32_t so = (uint32_t)(r * 64 + ((ch ^ (r & 3)) << 4));
        CP16(sA + so, Ag + (size_t)r * 1024 + ch * 8);
        CP16(sB + so, Bg + (size_t)r * 1024 + ch * 8);
    }
}

template<int MODE>
__global__ __launch_bounds__(128, 2) void mm_fp16(
    const __half* __restrict__ A, const __half* __restrict__ Bw,
    float* __restrict__ Out)
{
    extern __shared__ __half smh[];

    const int tid    = threadIdx.x;
    const int m_base = blockIdx.y * 128;
    const int n_base = blockIdx.x * 128;

    const __half* Ag = A  + (size_t)m_base * 1024;
    const __half* Bg = Bw + (size_t)n_base * 1024;

    const int warp = tid >> 5;
    const int lane = tid & 31;
    const int wm = warp & 1;           // rows wm*64
    const int wn = warp >> 1;          // cols wn*64
    const int g  = lane >> 2;
    const int tg = lane & 3;

    float acc[4][8][4];
#pragma unroll
    for (int mi = 0; mi < 4; mi++)
#pragma unroll
        for (int ni = 0; ni < 8; ni++)
#pragma unroll
            for (int j = 0; j < 4; j++) acc[mi][ni][j] = 0.0f;

    const uint32_t sb = smem_u32(smh);
#pragma unroll
    for (int p = 0; p < 2; ++p) {
        mmh_stage(sb + p * MMH_STAGE_BYTES,
                  sb + 3 * MMH_STAGE_BYTES + p * MMH_STAGE_BYTES,
                  Ag + p * 32, Bg + p * 32, tid);
        CP_COMMIT;
    }

    int sidx = 0;
    for (int kt = 0; kt < 32; ++kt) {
        CP_WAIT1;
        __syncthreads();

        {
            int ps = sidx + 2; if (ps >= 3) ps -= 3;
            if (kt + 2 < 32)
                mmh_stage(sb + ps * MMH_STAGE_BYTES,
                          sb + 3 * MMH_STAGE_BYTES + ps * MMH_STAGE_BYTES,
                          Ag + (kt + 2) * 32, Bg + (kt + 2) * 32, tid);
            CP_COMMIT;
        }

        const __half* Asb = smh + sidx * 4096;
        const __half* Bsb = smh + 12288 + sidx * 4096;

        uint4 af[4][2], bf[8];
#pragma unroll
        for (int mi = 0; mi < 4; mi++) {
            int r0 = wm * 64 + mi * 16 + g;
            af[mi][0] = *(const uint4*)&Asb[r0 * 32 + ((tg ^ (r0 & 3)) << 3)];
            int r1 = r0 + 8;
            af[mi][1] = *(const uint4*)&Asb[r1 * 32 + ((tg ^ (r1 & 3)) << 3)];
        }
#pragma unroll
        for (int ni = 0; ni < 8; ni++) {
            int rb = wn * 64 + ni * 8 + g;
            bf[ni] = *(const uint4*)&Bsb[rb * 32 + ((tg ^ (rb & 3)) << 3)];
        }
#pragma unroll
        for (int mi = 0; mi < 4; mi++)
#pragma unroll
            for (int ni = 0; ni < 8; ni++) {
                mma_fp16(acc[mi][ni],
                         af[mi][0].x, af[mi][1].x, af[mi][0].y, af[mi][1].y,
                         bf[ni].x, bf[ni].y);
                mma_fp16(acc[mi][ni],
                         af[mi][0].z, af[mi][1].z, af[mi][0].w, af[mi][1].w,
                         bf[ni].z, bf[ni].w);
            }
        if (++sidx == 3) sidx = 0;
    }

    // epilogue: warp n-tile = 64 cols, 64-aligned -> single head / part
    {
        const int n0   = n_base + wn * 64;
        const int part = n0 >> 10;
        const int h    = (n0 & 1023) >> 6;
#pragma unroll
        for (int mi = 0; mi < 4; mi++) {
            int row0 = m_base + wm * 64 + mi * 16 + g;
#pragma unroll
            for (int ni = 0; ni < 8; ni++) {
                if (MODE == 0) {
                    int d0 = ni * 8 + 2 * tg;
                    int i0 = d0 >> 1;
#pragma unroll
                    for (int half = 0; half < 2; half++) {
                        int m = row0 + half * 8;
                        int b = m >> 11, s = m & 2047;
                        float v0 = acc[mi][ni][half * 2 + 0];
                        float v1 = acc[mi][ni][half * 2 + 1];
                        size_t rowoff = ((size_t)(b * NHEAD + h) * S_LEN + s) * HDIM;
                        if (part == 2) {
                            *(__half2*)(g_v + rowoff + d0) =
                                __float22half2_rn(make_float2(v0, v1));
                        } else {
                            float cs = g_cos[s * 32 + i0], sn = g_sin[s * 32 + i0];
                            float r0 = v0 * cs - v1 * sn;
                            float r1 = v0 * sn + v1 * cs;
                            if (part == 0) { r0 *= 0.125f; r1 *= 0.125f; }
                            int pcol = ((ni >= 4) ? 32 : 0) + 8 * tg + 2 * (ni & 3);
                            __half* dsth = (part == 0) ? g_q : g_k;
                            *(__half2*)(dsth + rowoff + pcol) =
                                __float22half2_rn(make_float2(r0, r1));
                        }
                    }
                } else {
                    int coln = n0 + ni * 8 + 2 * tg;
#pragma unroll
                    for (int half = 0; half < 2; half++) {
                        int m = row0 + half * 8;
                        *(float2*)(Out + (size_t)m * 1024 + coln)
                            = make_float2(acc[mi][ni][half * 2 + 0],
                                          acc[mi][ni][half * 2 + 1]);
                    }
                }
            }
        }
    }
}

// ---------------------------------------------------------------------------
// fp16 tensor-core flash attention (m16n8k16). 128 threads = 4 warps, warp
// owns 32 q-rows (2 m-subtiles) -> K-tile B-fragments amortized over 2x MMAs.
// q-tile 128 rows, k-tile 64 keys, 2-stage cp.async, ONE barrier per k-tile.
// Q/K fp16 kperm'd; V row-major pad-72-half rows, ldmatrix.x4.trans B-frags.
// Q pre-scaled by 1/8. Epilogue -> g_attn fp16 kperm'd.
// ---------------------------------------------------------------------------
// smem bytes: Qs 16384 | Ks 2x8192 | Vs 2x9216 | PM 2x256  = 51712
#define ATTN_QS   0
#define ATTN_KS   16384
#define ATTN_VS   32768
#define ATTN_PM   51200
#define ATTN_SM_BYTES 51712

__device__ __forceinline__ void stage_kv_h(
    uint32_t kdst, uint32_t vdst, uint32_t pmdst,
    const __half* Kg, const __half* Vg, const float* Bsrc, int tid)
{
#pragma unroll
    for (int i = 0; i < 4; ++i) {
        int idx = tid + i * 128;       // 0..511
        int row = idx >> 3;            // key 0..63
        int ch  = idx & 7;             // 16B chunk
        CP16(kdst + row * 128 + ((ch ^ (row & 7)) << 4), Kg + (size_t)row * 64 + ch * 8);
        CP16(vdst + row * 144 + (ch << 4),               Vg + (size_t)row * 64 + ch * 8);
    }
    if (tid < 16) CP16(pmdst + tid * 16, Bsrc + tid * 4);
}

__global__ __launch_bounds__(128, 2) void attn_tc()
{
    extern __shared__ char smc[];
    const uint32_t base = smem_u32(smc);
    float* PMf = (float*)(smc + ATTN_PM);

    const int qt    = 15 - (int)blockIdx.x;         // heavy tiles first
    const int qbase = qt * 128;
    const int bh = blockIdx.y;
    const int b  = bh >> 4, h = bh & 15;
    const int tid  = threadIdx.x;
    const int warp = tid >> 5, lane = tid & 31;
    const int g = lane >> 2, tg = lane & 3;
    const int nkt = 2 * (qt + 1);

    const __half* Qg = g_q + ((size_t)bh * S_LEN + qbase) * HDIM;
    const __half* Kg = g_k + (size_t)bh * S_LEN * HDIM;
    const __half* Vg = g_v + (size_t)bh * S_LEN * HDIM;
    const float*  Bg = g_bias + b * S_LEN;

    stage_kv_h(base + ATTN_KS, base + ATTN_VS, base + ATTN_PM, Kg, Vg, Bg, tid);
    CP_COMMIT;

    // stage Q [128 rows x 128B], swizzle ch^(row&7)
#pragma unroll
    for (int r = 0; r < 8; ++r) {
        int idx = tid + r * 128;
        int row = idx >> 3, ch = idx & 7;
        *(uint4*)(smc + ATTN_QS + row * 128 + ((ch ^ (row & 7)) << 4))
            = *(const uint4*)(Qg + (size_t)row * 64 + ch * 8);
    }

    float S[2][8][4], O[2][8][4], mrow[2][2], lrow[2][2];
#pragma unroll
    for (int mt = 0; mt < 2; mt++) {
        mrow[mt][0] = mrow[mt][1] = -INFINITY;
        lrow[mt][0] = lrow[mt][1] = 0.0f;
#pragma unroll
        for (int t = 0; t < 8; t++)
#pragma unroll
            for (int j = 0; j < 4; j++) O[mt][t][j] = 0.0f;
    }

    const int wrow0 = qbase + warp * 32;
    const int kl  = lane & 15;              // ldmatrix key lane
    const int dh  = lane >> 4;              // ldmatrix d-half (0/1)

    for (int kt = 0; kt < nkt; ++kt) {
        const int buf   = kt & 1;
        const int kbase = kt * 64;

        CP_WAIT0;
        __syncthreads();

        if (kt + 1 < nkt) {
            int nb  = buf ^ 1;
            int kb2 = (kt + 1) * 64;
            stage_kv_h(base + ATTN_KS + nb * 8192, base + ATTN_VS + nb * 9216,
                       base + ATTN_PM + nb * 256,
                       Kg + (size_t)kb2 * 64, Vg + (size_t)kb2 * 64, Bg + kb2, tid);
        }
        CP_COMMIT;

        if (kbase <= wrow0 + 31) {     // per-warp causal tile skip
            const char* Kb = smc + ATTN_KS + buf * 8192;
            const float* PMb = PMf + buf * 64;

            // ---- S = Q K^T (fp16 m16n8k16, q pre-scaled by 1/8)
#pragma unroll
            for (int mt = 0; mt < 2; mt++)
#pragma unroll
                for (int nt = 0; nt < 8; nt++)
#pragma unroll
                    for (int j = 0; j < 4; j++) S[mt][nt][j] = 0.0f;

            const int qr0 = warp * 32 + g;
#pragma unroll
            for (int blk = 0; blk < 2; ++blk) {
                const int c = blk * 4 + tg;
                uint4 a00 = *(const uint4*)(smc + ATTN_QS + (qr0     ) * 128 + ((c ^ (qr0 & 7)) << 4));
                uint4 a01 = *(const uint4*)(smc + ATTN_QS + (qr0 +  8) * 128 + ((c ^ (qr0 & 7)) << 4));
                uint4 a10 = *(const uint4*)(smc + ATTN_QS + (qr0 + 16) * 128 + ((c ^ (qr0 & 7)) << 4));
                uint4 a11 = *(const uint4*)(smc + ATTN_QS + (qr0 + 24) * 128 + ((c ^ (qr0 & 7)) << 4));
#pragma unroll
                for (int nt = 0; nt < 8; ++nt) {
                    int krow = nt * 8 + g;
                    uint4 bf = *(const uint4*)(Kb + krow * 128 + ((c ^ g) << 4));
                    mma_fp16(S[0][nt], a00.x, a01.x, a00.y, a01.y, bf.x, bf.y);
                    mma_fp16(S[0][nt], a00.z, a01.z, a00.w, a01.w, bf.z, bf.w);
                    mma_fp16(S[1][nt], a10.x, a11.x, a10.y, a11.y, bf.x, bf.y);
                    mma_fp16(S[1][nt], a10.z, a11.z, a10.w, a11.w, bf.z, bf.w);
                }
            }

            // ---- mask + online softmax -> packed fp16 P fragments
            float2 pmb[8];
#pragma unroll
            for (int nt = 0; nt < 8; nt++)
                pmb[nt] = *(const float2*)&PMb[nt * 8 + 2 * tg];

            const bool do_causal = (kbase + 63 > wrow0);
            uint32_t pa_lo[2][8], pa_hi[2][8];

#pragma unroll
            for (int mt = 0; mt < 2; mt++) {
                int row_lo = wrow0 + mt * 16 + g;
                int row_hi = row_lo + 8;
                float mx_lo = -INFINITY, mx_hi = -INFINITY;
#pragma unroll
                for (int nt = 0; nt < 8; nt++) {
                    int col0 = kbase + nt * 8 + 2 * tg;
                    float v0 = S[mt][nt][0] + pmb[nt].x;
                    float v1 = S[mt][nt][1] + pmb[nt].y;
                    float v2 = S[mt][nt][2] + pmb[nt].x;
                    float v3 = S[mt][nt][3] + pmb[nt].y;
                    if (do_causal) {
                        if (col0     > row_lo) v0 = -1e30f;
                        if (col0 + 1 > row_lo) v1 = -1e30f;
                        if (col0     > row_hi) v2 = -1e30f;
                        if (col0 + 1 > row_hi) v3 = -1e30f;
                    }
                    S[mt][nt][0] = v0; S[mt][nt][1] = v1;
                    S[mt][nt][2] = v2; S[mt][nt][3] = v3;
                    mx_lo = fmaxf(mx_lo, fmaxf(v0, v1));
                    mx_hi = fmaxf(mx_hi, fmaxf(v2, v3));
                }
                mx_lo = fmaxf(mx_lo, __shfl_xor_sync(0xffffffffu, mx_lo, 1));
                mx_lo = fmaxf(mx_lo, __shfl_xor_sync(0xffffffffu, mx_lo, 2));
                mx_hi = fmaxf(mx_hi, __shfl_xor_sync(0xffffffffu, mx_hi, 1));
                mx_hi = fmaxf(mx_hi, __shfl_xor_sync(0xffffffffu, mx_hi, 2));

                float mn_lo = fmaxf(mrow[mt][0], mx_lo);
                float mn_hi = fmaxf(mrow[mt][1], mx_hi);
                float al_lo = __expf(mrow[mt][0] - mn_lo);
                float al_hi = __expf(mrow[mt][1] - mn_hi);

                float s_lo = 0.0f, s_hi = 0.0f;
#pragma unroll
                for (int nt = 0; nt < 8; nt++) {
                    float p0 = __expf(S[mt][nt][0] - mn_lo);
                    float p1 = __expf(S[mt][nt][1] - mn_lo);
                    float p2 = __expf(S[mt][nt][2] - mn_hi);
                    float p3 = __expf(S[mt][nt][3] - mn_hi);
                    s_lo += p0 + p1;
                    s_hi += p2 + p3;
                    pa_lo[mt][nt] = pack_h2(p0, p1);
                    pa_hi[mt][nt] = pack_h2(p2, p3);
                }
                s_lo += __shfl_xor_sync(0xffffffffu, s_lo, 1);
                s_lo += __shfl_xor_sync(0xffffffffu, s_lo, 2);
                s_hi += __shfl_xor_sync(0xffffffffu, s_hi, 1);
                s_hi += __shfl_xor_sync(0xffffffffu, s_hi, 2);

                lrow[mt][0] = lrow[mt][0] * al_lo + s_lo;
                lrow[mt][1] = lrow[mt][1] * al_hi + s_hi;
                mrow[mt][0] = mn_lo;
                mrow[mt][1] = mn_hi;
#pragma unroll
                for (int hd = 0; hd < 8; hd++) {
                    O[mt][hd][0] *= al_lo;
                    O[mt][hd][1] *= al_lo;
                    O[mt][hd][2] *= al_hi;
                    O[mt][hd][3] *= al_hi;
                }
            }

            // ---- O += P V  (B-frags via ldmatrix.x4.trans, shared across mt)
            const uint32_t vb = base + ATTN_VS + buf * 9216;
#pragma unroll
            for (int kb = 0; kb < 4; ++kb) {
#pragma unroll
                for (int dp = 0; dp < 4; ++dp) {
                    uint32_t addr = vb + (kb * 16 + kl) * 144 + dp * 32 + dh * 16;
                    uint32_t r0, r1, r2, r3;
                    LDSM_X4_T(r0, r1, r2, r3, addr);
#pragma unroll
                    for (int mt = 0; mt < 2; mt++) {
                        uint32_t a0 = pa_lo[mt][2 * kb],     a1 = pa_hi[mt][2 * kb];
                        uint32_t a2 = pa_lo[mt][2 * kb + 1], a3 = pa_hi[mt][2 * kb + 1];
                        mma_fp16(O[mt][2 * dp],     a0, a1, a2, a3, r0, r1);
                        mma_fp16(O[mt][2 * dp + 1], a0, a1, a2, a3, r2, r3);
                    }
                }
            }
        }
    }

    // epilogue: normalize + write g_attn fp16 at permuted k positions.
#pragma unroll
    for (int mt = 0; mt < 2; mt++) {
        float inv_lo = 1.0f / lrow[mt][0];
        float inv_hi = 1.0f / lrow[mt][1];
        int row_lo = wrow0 + mt * 16 + g;
#pragma unroll
        for (int hd = 0; hd < 8; hd++) {
            int pcol = h * 64 + (hd >> 2) * 32 + 8 * tg + 2 * (hd & 3);
            *(__half2*)(g_attn + ((size_t)b * S_LEN + row_lo) * D_MODEL + pcol) =
                __float22half2_rn(make_float2(O[mt][hd][0] * inv_lo, O[mt][hd][1] * inv_lo));
            *(__half2*)(g_attn + ((size_t)b * S_LEN + row_lo + 8) * D_MODEL + pcol) =
                __float22half2_rn(make_float2(O[mt][hd][2] * inv_hi, O[mt][hd][3] * inv_hi));
        }
    }
}

// ---------------------------------------------------------------------------
extern "C" void kernel_launch(void* const* d_in, const int* in_sizes, int n_in,
                              void* d_out, int out_size)
{
    const float* x      = (const float*)d_in[0];
    const int*   pmask  = (const int*)d_in[1];
    const float* w_qkv  = (const float*)d_in[2];
    const float* w_o    = (const float*)d_in[3];
    float*       out    = (float*)d_out;

    cudaFuncSetAttribute(attn_tc,
                         cudaFuncAttributeMaxDynamicSharedMemorySize, ATTN_SM_BYTES);
    cudaFuncSetAttribute(mm_fp16<0>,
                         cudaFuncAttributeMaxDynamicSharedMemorySize, MMH_SM_BYTES);
    cudaFuncSetAttribute(mm_fp16<1>,
                         cudaFuncAttributeMaxDynamicSharedMemorySize, MMH_SM_BYTES);

    __half *xc, *wc, *woc, *attn_ptr;
    cudaGetSymbolAddress((void**)&xc, g_xc);
    cudaGetSymbolAddress((void**)&wc, g_wc);
    cudaGetSymbolAddress((void**)&woc, g_woc);
    cudaGetSymbolAddress((void**)&attn_ptr, g_attn);

    rope_table_kernel<<<(S_LEN * 32 + 255) / 256, 256>>>();
    cvt_all_kernel<<<(N2_X + N2_W + N2_WO + 255) / 256, 256>>>(
        (const float2*)x, (const float2*)w_qkv, (const float2*)w_o);
    bias_kernel<<<(BATCH * S_LEN + 255) / 256, 256>>>(pmask);

    // QKV projection + RoPE: M=8192, N=3072 (fp16 TC, 64x64 warp tiles)
    mm_fp16<0><<<dim3(3 * D_MODEL / 128, (BATCH * S_LEN) / 128), 128, MMH_SM_BYTES>>>(xc, wc, nullptr);
    // Flash attention (fp16 m16n8k16, 32-row warps)
    attn_tc<<<dim3(16, BH), 128, ATTN_SM_BYTES>>>();
    // Output projection: M=8192, N=1024
    mm_fp16<1><<<dim3(D_MODEL / 128, (BATCH * S_LEN) / 128), 128, MMH_SM_BYTES>>>(attn_ptr, woc, out);
}